// round 1
// baseline (speedup 1.0000x reference)
#include <cuda_runtime.h>

#define BATCH 8
#define TLEN 64000
#define NFR 251
#define NB 513
#define NCH 32
#define NNODES 250
#define NODE_DIM 4116
#define SCC 20
#define EPSV 1e-5f

// ---------------- scratch (device globals; no allocation) ----------------
__device__ float g_s[BATCH * NB * NFR];
__device__ float g_h1[(long)BATCH * NCH * NB * NFR];
__device__ float g_h2[(long)BATCH * NCH * NB * NFR];
__device__ float g_nodes[BATCH * NNODES * NODE_DIM];
__device__ float g_gh[BATCH * NNODES * 512];
__device__ float g_ssrc[BATCH * NNODES * 8];
__device__ float g_sdst[BATCH * NNODES * 8];
__device__ float g_g1[BATCH * NNODES * 512];
__device__ float g_h2g[BATCH * NNODES * 32];
__device__ float g_s2src[BATCH * NNODES];
__device__ float g_s2dst[BATCH * NNODES];
__device__ float g_g2[BATCH * NNODES * 32];

// ---------------- sinc conv (only first 1000 outputs needed) ----------------
__global__ void k_sinc(const float* __restrict__ x, const float* __restrict__ w) {
    __shared__ float sw[1024];
    __shared__ float sx[1536];
    int b = blockIdx.x / SCC, c = blockIdx.x % SCC;
    for (int i = threadIdx.x; i < 1024; i += 256) sw[i] = w[c * 1024 + i];
    for (int i = threadIdx.x; i < 1536; i += 256)
        sx[i] = (i < 1512) ? x[b * TLEN + i] : 0.f;
    __syncthreads();
    for (int t = threadIdx.x; t < NNODES; t += 256) {
        float acc = 0.f;
        for (int q = 0; q < 4; q++) {
            int p = 4 * t + q;
            int k0 = 512 - p; if (k0 < 0) k0 = 0;
            const float* xs = sx + p - 512;
            for (int k = k0; k < 1024; k++) acc = fmaf(sw[k], xs[k], acc);
        }
        g_nodes[(b * NNODES + t) * NODE_DIM + c] = acc * 0.25f;
    }
}

// ---------------- STFT: 1024-pt radix-2 FFT per frame ----------------
__global__ void k_stft(const float* __restrict__ x) {
    __shared__ float re[1024], im[1024];
    int b = blockIdx.x / NFR, fr = blockIdx.x % NFR;
    int base = fr * 256 - 512;
    for (int n = threadIdx.x; n < 1024; n += 512) {
        int m = base + n;
        if (m < 0) m = -m;
        else if (m >= TLEN) m = 2 * TLEN - 2 - m;
        int r = (int)(__brev((unsigned)n) >> 22);
        re[r] = x[b * TLEN + m];
        im[r] = 0.f;
    }
    __syncthreads();
    int t = threadIdx.x;
    for (int len = 2; len <= 1024; len <<= 1) {
        int half = len >> 1;
        int j = t & (half - 1);
        int pos = (t / half) * len + j;
        float ang = -6.283185307179586f * (float)j / (float)len;
        float si, co;
        sincosf(ang, &si, &co);
        float ur = re[pos], ui = im[pos];
        float vr = re[pos + half], vi = im[pos + half];
        float tr = vr * co - vi * si;
        float ti = vr * si + vi * co;
        re[pos] = ur + tr; im[pos] = ui + ti;
        re[pos + half] = ur - tr; im[pos + half] = ui - ti;
        __syncthreads();
    }
    for (int k = t; k <= 512; k += 512) {
        float mg = sqrtf(re[k] * re[k] + im[k] * im[k]);
        g_s[(b * NB + k) * NFR + fr] = logf(mg + 1e-9f);
    }
}

// ---------------- conv1 (1->32) + BN + ReLU ----------------
__global__ void k_conv1(const float* __restrict__ w, const float* __restrict__ cb,
                        const float* __restrict__ g, const float* __restrict__ bb) {
    long idx = (long)blockIdx.x * 256 + threadIdx.x;
    const long SP = (long)NB * NFR;
    if (idx >= (long)BATCH * NCH * SP) return;
    int xx = (int)(idx % NFR);
    long r1 = idx / NFR;
    int y = (int)(r1 % NB);
    long r2 = r1 / NB;
    int co = (int)(r2 % NCH);
    int b = (int)(r2 / NCH);
    float acc = cb[co];
    const float* sp = g_s + b * SP;
#pragma unroll
    for (int ky = 0; ky < 3; ky++) {
        int yy = y + ky - 1;
        if (yy < 0 || yy >= NB) continue;
#pragma unroll
        for (int kx = 0; kx < 3; kx++) {
            int xk = xx + kx - 1;
            if (xk < 0 || xk >= NFR) continue;
            acc = fmaf(w[co * 9 + ky * 3 + kx], sp[(long)yy * NFR + xk], acc);
        }
    }
    float sc = g[co] * rsqrtf(1.f + EPSV);
    acc = acc * sc + bb[co];
    g_h1[idx] = acc > 0.f ? acc : 0.f;
}

// ---------------- conv2 (32->32) + BN + ReLU, smem tiled ----------------
// block: 256 threads (co = tid&31, yy = tid>>5); tile 8y x 32x outputs
__global__ void k_conv2(const float* __restrict__ w, const float* __restrict__ cb,
                        const float* __restrict__ g, const float* __restrict__ bb) {
    extern __shared__ float smem[];
    float* tile = smem;             // [32][10][34] = 10880
    float* swt = smem + 10880;      // [ci][ky][kx][co] = 9216
    int x0 = blockIdx.x * 32, y0 = blockIdx.y * 8, b = blockIdx.z;
    int tid = threadIdx.x;
    for (int i = tid; i < 32 * 32 * 9; i += 256) {
        int co = i & 31; int rest = i >> 5;
        int kx = rest % 3; int ky = (rest / 3) % 3; int ci = rest / 9;
        swt[i] = w[((co * 32 + ci) * 3 + ky) * 3 + kx];
    }
    const long SP = (long)NB * NFR;
    for (int i = tid; i < 32 * 10 * 34; i += 256) {
        int cc = i % 34; int rr = (i / 34) % 10; int ci = i / 340;
        int gy = y0 - 1 + rr, gx = x0 - 1 + cc;
        float v = 0.f;
        if (gy >= 0 && gy < NB && gx >= 0 && gx < NFR)
            v = g_h1[(b * NCH + ci) * SP + (long)gy * NFR + gx];
        tile[i] = v;
    }
    __syncthreads();
    int co = tid & 31, yy = tid >> 5;
    float acc[32];
    float cbias = cb[co];
#pragma unroll
    for (int i = 0; i < 32; i++) acc[i] = cbias;
    for (int ci = 0; ci < 32; ci++) {
        const float* tci = tile + ci * 340;
#pragma unroll
        for (int ky = 0; ky < 3; ky++) {
            const float* row = tci + (yy + ky) * 34;
            float r[34];
#pragma unroll
            for (int q = 0; q < 34; q++) r[q] = row[q];
#pragma unroll
            for (int kx = 0; kx < 3; kx++) {
                float wv = swt[((ci * 3 + ky) * 3 + kx) * 32 + co];
#pragma unroll
                for (int q = 0; q < 32; q++) acc[q] = fmaf(wv, r[q + kx], acc[q]);
            }
        }
    }
    float sc = g[co] * rsqrtf(1.f + EPSV);
    float bbv = bb[co];
    int y = y0 + yy;
    if (y < NB) {
        float* outp = g_h2 + (b * NCH + co) * SP + (long)y * NFR;
#pragma unroll
        for (int q = 0; q < 32; q++) {
            int xv = x0 + q;
            if (xv < NFR) {
                float v = acc[q] * sc + bbv;
                outp[xv] = v > 0.f ? v : 0.f;
            }
        }
    }
}

// ---------------- 2x2 maxpool + scatter into node features ----------------
__global__ void k_pool() {
    int idx = blockIdx.x * 256 + threadIdx.x;
    if (idx >= BATCH * NNODES * 4096) return;
    int j = idx & 4095;
    int t = (idx >> 12) % NNODES;
    int b = (idx >> 12) / NNODES;
    int tp = t >> 1;
    int o = ((t & 1) << 12) + j;
    int c = o >> 8;
    int f = o & 255;
    const long SP = (long)NB * NFR;
    const float* p = g_h2 + (b * NCH + c) * SP + (long)(2 * f) * NFR + 2 * tp;
    float m = fmaxf(fmaxf(p[0], p[1]), fmaxf(p[NFR], p[NFR + 1]));
    g_nodes[(b * NNODES + t) * NODE_DIM + SCC + j] = m;
}

// ---------------- generic tiled SGEMM (64x64x16, 4x4 microtile) ----------------
__device__ __forceinline__ void gemm_body(const float* __restrict__ A,
                                          const float* __restrict__ B,
                                          float* __restrict__ C,
                                          int M, int N, int K) {
    __shared__ float As[16][65];
    __shared__ float Bs[16][64];
    int bx = blockIdx.x, by = blockIdx.y;
    int tid = threadIdx.x;
    int tr = tid >> 4, tc = tid & 15;
    float acc[4][4] = {};
    for (int k0 = 0; k0 < K; k0 += 16) {
        for (int i = tid; i < 64 * 16; i += 256) {
            int m = i >> 4, kk = i & 15;
            int gm = by * 64 + m, gk = k0 + kk;
            As[kk][m] = (gm < M && gk < K) ? A[(long)gm * K + gk] : 0.f;
        }
        for (int i = tid; i < 16 * 64; i += 256) {
            int kk = i >> 6, n = i & 63;
            int gk = k0 + kk, gn = bx * 64 + n;
            Bs[kk][n] = (gk < K && gn < N) ? B[(long)gk * N + gn] : 0.f;
        }
        __syncthreads();
#pragma unroll
        for (int kk = 0; kk < 16; kk++) {
            float a[4], bv[4];
#pragma unroll
            for (int i = 0; i < 4; i++) a[i] = As[kk][tr * 4 + i];
#pragma unroll
            for (int jq = 0; jq < 4; jq++) bv[jq] = Bs[kk][tc * 4 + jq];
#pragma unroll
            for (int i = 0; i < 4; i++)
#pragma unroll
                for (int jq = 0; jq < 4; jq++)
                    acc[i][jq] = fmaf(a[i], bv[jq], acc[i][jq]);
        }
        __syncthreads();
    }
    for (int i = 0; i < 4; i++) {
        int gm = by * 64 + tr * 4 + i;
        if (gm >= M) continue;
        for (int jq = 0; jq < 4; jq++) {
            int gn = bx * 64 + tc * 4 + jq;
            if (gn < N) C[(long)gm * N + gn] = acc[i][jq];
        }
    }
}
__global__ void k_gemm1(const float* __restrict__ W) {
    gemm_body(g_nodes, W, g_gh, BATCH * NNODES, 512, NODE_DIM);
}
__global__ void k_gemm2(const float* __restrict__ W) {
    gemm_body(g_g1, W, g_h2g, BATCH * NNODES, 32, 512);
}

// ---------------- GAT1 attention scores ----------------
__global__ void k_scores1(const float* __restrict__ asrc, const float* __restrict__ adst) {
    int idx = blockIdx.x * 256 + threadIdx.x;
    if (idx >= BATCH * NNODES * 8) return;
    int h = idx & 7;
    int bn = idx >> 3;
    const float* hp = g_gh + (long)bn * 512 + h * 64;
    float s1 = 0.f, s2 = 0.f;
    for (int f = 0; f < 64; f++) {
        float v = hp[f];
        s1 = fmaf(v, asrc[h * 64 + f], s1);
        s2 = fmaf(v, adst[h * 64 + f], s2);
    }
    g_ssrc[idx] = s1;
    g_sdst[idx] = s2;
}

// ---------------- GAT1 softmax-attention + aggregate (10 i per block) ----------------
__global__ void k_att1(const float* __restrict__ bias) {
    extern __shared__ float sm[];
    float* swj = sm;               // [10][250][8] = 20000
    float* ss = sm + 20000;        // 2000
    float* sums = sm + 22000;      // 80
    int b = blockIdx.x / 25, ig = blockIdx.x % 25;
    int i0 = ig * 10;
    int tid = threadIdx.x;
    for (int i = tid; i < 2000; i += 256) ss[i] = g_ssrc[b * 2000 + i];
    __syncthreads();
    int warp = tid >> 5, lane = tid & 31;
    for (int task = warp; task < 80; task += 8) {
        int ii = task >> 3, h = task & 7;
        float d = g_sdst[(b * NNODES + i0 + ii) * 8 + h];
        float mx = -1e30f;
        for (int j = lane; j < NNODES; j += 32) {
            float e = d + ss[j * 8 + h];
            e = e > 0.f ? e : 0.2f * e;
            mx = fmaxf(mx, e);
        }
#pragma unroll
        for (int o = 16; o; o >>= 1) mx = fmaxf(mx, __shfl_xor_sync(0xffffffffu, mx, o));
        float smv = 0.f;
        for (int j = lane; j < NNODES; j += 32) {
            float e = d + ss[j * 8 + h];
            e = e > 0.f ? e : 0.2f * e;
            float wv = expf(e - mx);
            swj[(ii * NNODES + j) * 8 + h] = wv;
            smv += wv;
        }
#pragma unroll
        for (int o = 16; o; o >>= 1) smv += __shfl_xor_sync(0xffffffffu, smv, o);
        if (!lane) sums[ii * 8 + h] = smv;
    }
    __syncthreads();
    float acc0[10], acc1[10];
#pragma unroll
    for (int ii = 0; ii < 10; ii++) { acc0[ii] = 0.f; acc1[ii] = 0.f; }
    const float* Hb = g_gh + (long)b * NNODES * 512;
    int f0 = tid, f1 = tid + 256;
    int h0 = f0 >> 6, h1 = f1 >> 6;
    for (int j = 0; j < NNODES; j++) {
        float v0 = Hb[j * 512 + f0];
        float v1 = Hb[j * 512 + f1];
#pragma unroll
        for (int ii = 0; ii < 10; ii++) {
            acc0[ii] = fmaf(swj[(ii * NNODES + j) * 8 + h0], v0, acc0[ii]);
            acc1[ii] = fmaf(swj[(ii * NNODES + j) * 8 + h1], v1, acc1[ii]);
        }
    }
    float bi0 = bias[f0], bi1 = bias[f1];
    for (int ii = 0; ii < 10; ii++) {
        int i = i0 + ii;
        float* op = g_g1 + (long)(b * NNODES + i) * 512;
        float o0 = acc0[ii] / sums[ii * 8 + h0] + bi0;
        float o1 = acc1[ii] / sums[ii * 8 + h1] + bi1;
        op[f0] = o0 > 0.f ? o0 : 0.f;
        op[f1] = o1 > 0.f ? o1 : 0.f;
    }
}

// ---------------- GAT2 scores ----------------
__global__ void k_scores2(const float* __restrict__ asrc, const float* __restrict__ adst) {
    int idx = blockIdx.x * 256 + threadIdx.x;
    if (idx >= BATCH * NNODES) return;
    const float* hp = g_h2g + (long)idx * 32;
    float s1 = 0.f, s2 = 0.f;
    for (int f = 0; f < 32; f++) {
        float v = hp[f];
        s1 = fmaf(v, asrc[f], s1);
        s2 = fmaf(v, adst[f], s2);
    }
    g_s2src[idx] = s1;
    g_s2dst[idx] = s2;
}

// ---------------- GAT2 attention + aggregate ----------------
__global__ void k_att2(const float* __restrict__ bias) {
    __shared__ float sh[NNODES * 32];
    __shared__ float ssr[NNODES];
    __shared__ float wjs[8][NNODES];
    int b = blockIdx.x;
    int tid = threadIdx.x, warp = tid >> 5, lane = tid & 31;
    for (int i = tid; i < NNODES * 32; i += 256) sh[i] = g_h2g[b * NNODES * 32 + i];
    for (int i = tid; i < NNODES; i += 256) ssr[i] = g_s2src[b * NNODES + i];
    __syncthreads();
    float bi = bias[lane];
    for (int i = warp; i < NNODES; i += 8) {
        float d = g_s2dst[b * NNODES + i];
        float mx = -1e30f;
        for (int j = lane; j < NNODES; j += 32) {
            float e = d + ssr[j];
            e = e > 0.f ? e : 0.2f * e;
            mx = fmaxf(mx, e);
        }
#pragma unroll
        for (int o = 16; o; o >>= 1) mx = fmaxf(mx, __shfl_xor_sync(0xffffffffu, mx, o));
        float sum = 0.f;
        for (int j = lane; j < NNODES; j += 32) {
            float e = d + ssr[j];
            e = e > 0.f ? e : 0.2f * e;
            float wv = expf(e - mx);
            wjs[warp][j] = wv;
            sum += wv;
        }
#pragma unroll
        for (int o = 16; o; o >>= 1) sum += __shfl_xor_sync(0xffffffffu, sum, o);
        __syncwarp();
        float acc = 0.f;
        for (int j = 0; j < NNODES; j++) acc = fmaf(wjs[warp][j], sh[j * 32 + lane], acc);
        g_g2[(b * NNODES + i) * 32 + lane] = acc / sum + bi;
    }
}

// ---------------- mean-pool + FC head ----------------
__global__ void k_head(const float* __restrict__ fc1w, const float* __restrict__ fc1b,
                       const float* __restrict__ bg, const float* __restrict__ bb2,
                       const float* __restrict__ fc2w, const float* __restrict__ fc2b,
                       float* __restrict__ out, int write_emb) {
    __shared__ float semb[32];
    __shared__ float sz[128];
    int b = blockIdx.x, tid = threadIdx.x;
    if (tid < 32) {
        float s = 0.f;
        for (int i = 0; i < NNODES; i++) s += g_g2[(b * NNODES + i) * 32 + tid];
        s *= (1.f / 250.f);
        semb[tid] = s;
        if (write_emb) out[16 + b * 32 + tid] = s;
    }
    __syncthreads();
    {
        float z = fc1b[tid];
        for (int f = 0; f < 32; f++) z = fmaf(semb[f], fc1w[f * 128 + tid], z);
        z = z * (bg[tid] * rsqrtf(1.f + EPSV)) + bb2[tid];
        sz[tid] = z > 0.f ? z : 0.f;
    }
    __syncthreads();
    if (tid < 2) {
        float o = fc2b[tid];
        for (int q = 0; q < 128; q++) o = fmaf(sz[q], fc2w[q * 2 + tid], o);
        out[b * 2 + tid] = o;
    }
}

extern "C" void kernel_launch(void* const* d_in, const int* in_sizes, int n_in,
                              void* d_out, int out_size) {
    const float* x = (const float*)d_in[0];
    const float* sinc_w = (const float*)d_in[1];
    const float* conv1_w = (const float*)d_in[2];
    const float* conv1_b = (const float*)d_in[3];
    const float* bn1_g = (const float*)d_in[4];
    const float* bn1_b = (const float*)d_in[5];
    const float* conv2_w = (const float*)d_in[6];
    const float* conv2_b = (const float*)d_in[7];
    const float* bn2_g = (const float*)d_in[8];
    const float* bn2_b = (const float*)d_in[9];
    const float* gat1_W = (const float*)d_in[10];
    const float* gat1_asrc = (const float*)d_in[11];
    const float* gat1_adst = (const float*)d_in[12];
    const float* gat1_bias = (const float*)d_in[13];
    const float* gat2_W = (const float*)d_in[14];
    const float* gat2_asrc = (const float*)d_in[15];
    const float* gat2_adst = (const float*)d_in[16];
    const float* gat2_bias = (const float*)d_in[17];
    const float* fc1_w = (const float*)d_in[18];
    const float* fc1_b = (const float*)d_in[19];
    const float* bnf_g = (const float*)d_in[20];
    const float* bnf_b = (const float*)d_in[21];
    const float* fc2_w = (const float*)d_in[22];
    const float* fc2_b = (const float*)d_in[23];

    cudaFuncSetAttribute(k_conv2, cudaFuncAttributeMaxDynamicSharedMemorySize, 20096 * 4);
    cudaFuncSetAttribute(k_att1, cudaFuncAttributeMaxDynamicSharedMemorySize, 22080 * 4);

    k_sinc<<<BATCH * SCC, 256>>>(x, sinc_w);
    k_stft<<<BATCH * NFR, 512>>>(x);

    long tot1 = (long)BATCH * NCH * NB * NFR;
    k_conv1<<<(unsigned)((tot1 + 255) / 256), 256>>>(conv1_w, conv1_b, bn1_g, bn1_b);

    dim3 gc2((NFR + 31) / 32, (NB + 7) / 8, BATCH);
    k_conv2<<<gc2, 256, 20096 * 4>>>(conv2_w, conv2_b, bn2_g, bn2_b);

    k_pool<<<(BATCH * NNODES * 4096 + 255) / 256, 256>>>();

    dim3 gg1(8, 32);
    k_gemm1<<<gg1, 256>>>(gat1_W);
    k_scores1<<<(BATCH * NNODES * 8 + 255) / 256, 256>>>(gat1_asrc, gat1_adst);
    k_att1<<<BATCH * 25, 256, 22080 * 4>>>(gat1_bias);

    dim3 gg2(1, 32);
    k_gemm2<<<gg2, 256>>>(gat2_W);
    k_scores2<<<(BATCH * NNODES + 255) / 256, 256>>>(gat2_asrc, gat2_adst);
    k_att2<<<BATCH, 256>>>(gat2_bias);

    int write_emb = (out_size >= 272) ? 1 : 0;
    k_head<<<BATCH, 128>>>(fc1_w, fc1_b, bnf_g, bnf_b, fc2_w, fc2_b,
                           (float*)d_out, write_emb);
}

// round 3
// speedup vs baseline: 1.0360x; 1.0360x over previous
#include <cuda_runtime.h>
#include <cstdint>

#define BATCH 8
#define TLEN 64000
#define NFR 251
#define NB 513
#define NCH 32
#define NNODES 250
#define NODE_DIM 4116
#define SCC 20
#define EPSV 1e-5f

// ---------------- scratch (device globals; no allocation) ----------------
__device__ float g_s[BATCH * NB * NFR];
__device__ float g_nodes[BATCH * NNODES * NODE_DIM];
__device__ float g_gh[BATCH * NNODES * 512];
__device__ float g_ssrc[BATCH * NNODES * 8];
__device__ float g_sdst[BATCH * NNODES * 8];
__device__ float g_g1[BATCH * NNODES * 512];
__device__ float g_h2g[BATCH * NNODES * 32];
__device__ float g_s2src[BATCH * NNODES];
__device__ float g_s2dst[BATCH * NNODES];
__device__ float g_g2[BATCH * NNODES * 32];

// ---------------- sinc conv (only first 1000 outputs needed) ----------------
__global__ void k_sinc(const float* __restrict__ x, const float* __restrict__ w) {
    __shared__ float sw[1024];
    __shared__ float sx[1536];
    int b = blockIdx.x / SCC, c = blockIdx.x % SCC;
    for (int i = threadIdx.x; i < 1024; i += 256) sw[i] = w[c * 1024 + i];
    for (int i = threadIdx.x; i < 1536; i += 256)
        sx[i] = (i < 1512) ? x[b * TLEN + i] : 0.f;
    __syncthreads();
    for (int t = threadIdx.x; t < NNODES; t += 256) {
        float acc = 0.f;
        for (int q = 0; q < 4; q++) {
            int p = 4 * t + q;
            int k0 = 512 - p; if (k0 < 0) k0 = 0;
            const float* xs = sx + p - 512;
            for (int k = k0; k < 1024; k++) acc = fmaf(sw[k], xs[k], acc);
        }
        g_nodes[(b * NNODES + t) * NODE_DIM + c] = acc * 0.25f;
    }
}

// ---------------- STFT: 1024-pt radix-2 FFT per frame ----------------
__global__ void k_stft(const float* __restrict__ x) {
    __shared__ float re[1024], im[1024];
    int b = blockIdx.x / NFR, fr = blockIdx.x % NFR;
    int base = fr * 256 - 512;
    for (int n = threadIdx.x; n < 1024; n += 512) {
        int m = base + n;
        if (m < 0) m = -m;
        else if (m >= TLEN) m = 2 * TLEN - 2 - m;
        int r = (int)(__brev((unsigned)n) >> 22);
        re[r] = x[b * TLEN + m];
        im[r] = 0.f;
    }
    __syncthreads();
    int t = threadIdx.x;
    for (int len = 2; len <= 1024; len <<= 1) {
        int half = len >> 1;
        int j = t & (half - 1);
        int pos = (t / half) * len + j;
        float ang = -6.283185307179586f * (float)j / (float)len;
        float si, co;
        sincosf(ang, &si, &co);
        float ur = re[pos], ui = im[pos];
        float vr = re[pos + half], vi = im[pos + half];
        float tr = vr * co - vi * si;
        float ti = vr * si + vi * co;
        re[pos] = ur + tr; im[pos] = ui + ti;
        re[pos + half] = ur - tr; im[pos + half] = ui - ti;
        __syncthreads();
    }
    for (int k = t; k <= 512; k += 512) {
        float mg = sqrtf(re[k] * re[k] + im[k] * im[k]);
        g_s[(b * NB + k) * NFR + fr] = logf(mg + 1e-9f);
    }
}

// ---------------- fused conv1 + conv2 + 2x2 maxpool + node scatter ----------
// block: 256 threads (co = tid&31, yy = tid>>5); tile 8y x 32x conv2 outputs
__global__ void k_fused(const float* __restrict__ w1, const float* __restrict__ b1,
                        const float* __restrict__ g1v, const float* __restrict__ be1,
                        const float* __restrict__ w2, const float* __restrict__ b2,
                        const float* __restrict__ g2v, const float* __restrict__ be2) {
    extern __shared__ float smem[];
    float* h1t = smem;              // [32][10][34] = 10880 (later reused as pm[8*16][33])
    float* wt2 = smem + 10880;      // [ci][ky][kx][co] = 9216
    float* sst = smem + 20096;      // s tile [12][36] = 432
    float* w1s = smem + 20528;      // conv1 weights 288
    int x0 = blockIdx.x * 32, y0 = blockIdx.y * 8, b = blockIdx.z;
    int tid = threadIdx.x;
    for (int i = tid; i < 32 * 32 * 9; i += 256) {
        int co = i & 31; int rest = i >> 5;
        int kx = rest % 3; int ky = (rest / 3) % 3; int ci = rest / 9;
        wt2[i] = w2[((co * 32 + ci) * 3 + ky) * 3 + kx];
    }
    for (int i = tid; i < 288; i += 256) w1s[i] = w1[i];
    for (int i = tid; i < 12 * 36; i += 256) {
        int cc = i % 36, rr = i / 36;
        int gy = y0 - 2 + rr, gx = x0 - 2 + cc;
        float v = 0.f;
        if (gy >= 0 && gy < NB && gx >= 0 && gx < NFR)
            v = g_s[(b * NB + gy) * NFR + gx];
        sst[i] = v;
    }
    __syncthreads();
    // conv1 -> h1 tile
    for (int i = tid; i < 10880; i += 256) {
        int cc = i % 34; int rr = (i / 34) % 10; int ci = i / 340;
        int y = y0 - 1 + rr, x = x0 - 1 + cc;
        float v = 0.f;
        if (y >= 0 && y < NB && x >= 0 && x < NFR) {
            float acc = b1[ci];
            const float* wp = w1s + ci * 9;
#pragma unroll
            for (int ky = 0; ky < 3; ky++)
#pragma unroll
                for (int kx = 0; kx < 3; kx++)
                    acc = fmaf(wp[ky * 3 + kx], sst[(rr + ky) * 36 + (cc + kx)], acc);
            float sc = g1v[ci] * rsqrtf(1.f + EPSV);
            acc = acc * sc + be1[ci];
            v = acc > 0.f ? acc : 0.f;
        }
        h1t[i] = v;
    }
    __syncthreads();
    int co = tid & 31, yy = tid >> 5;
    float acc[32];
    float cbias = b2[co];
#pragma unroll
    for (int i = 0; i < 32; i++) acc[i] = cbias;
    for (int ci = 0; ci < 32; ci++) {
        const float* tci = h1t + ci * 340;
#pragma unroll
        for (int ky = 0; ky < 3; ky++) {
            const float* row = tci + (yy + ky) * 34;
            float r[34];
#pragma unroll
            for (int q = 0; q < 34; q++) r[q] = row[q];
#pragma unroll
            for (int kx = 0; kx < 3; kx++) {
                float wv = wt2[((ci * 3 + ky) * 3 + kx) * 32 + co];
#pragma unroll
                for (int q = 0; q < 32; q++) acc[q] = fmaf(wv, r[q + kx], acc[q]);
            }
        }
    }
    // BN + ReLU + horizontal pair max
    float sc = g2v[co] * rsqrtf(1.f + EPSV);
    float bbv = be2[co];
    float hm[16];
#pragma unroll
    for (int q2 = 0; q2 < 16; q2++) {
        float v0 = acc[2 * q2] * sc + bbv;     v0 = v0 > 0.f ? v0 : 0.f;
        float v1 = acc[2 * q2 + 1] * sc + bbv; v1 = v1 > 0.f ? v1 : 0.f;
        hm[q2] = fmaxf(v0, v1);
    }
    __syncthreads();               // done with h1t as conv input
    float* pm = h1t;               // pm[(yy*16+tx)*33 + co], 4224 floats
#pragma unroll
    for (int q2 = 0; q2 < 16; q2++) pm[(yy * 16 + q2) * 33 + co] = hm[q2];
    __syncthreads();
    // vertical pair max + scatter float4 (4 pooled rows) into g_nodes
    int txh = tid >> 5;  // 0..7
#pragma unroll
    for (int t2 = 0; t2 < 2; t2++) {
        int txp = txh * 2 + t2;
        int tp = (x0 >> 1) + txp;
        if (tp < 125) {
            float4 v;
            v.x = fmaxf(pm[(0 * 16 + txp) * 33 + co], pm[(1 * 16 + txp) * 33 + co]);
            v.y = fmaxf(pm[(2 * 16 + txp) * 33 + co], pm[(3 * 16 + txp) * 33 + co]);
            v.z = fmaxf(pm[(4 * 16 + txp) * 33 + co], pm[(5 * 16 + txp) * 33 + co]);
            v.w = fmaxf(pm[(6 * 16 + txp) * 33 + co], pm[(7 * 16 + txp) * 33 + co]);
            int t = 2 * tp + (co >> 4);
            long off = (long)(b * NNODES + t) * NODE_DIM + SCC + (co & 15) * 256 + (y0 >> 1);
            *(float4*)(g_nodes + off) = v;
        }
    }
}

// ---------------- gemm1 via tf32 tensor cores --------------------------------
__device__ __forceinline__ uint32_t tf32r(float x) {
    uint32_t u;
    asm("cvt.rna.tf32.f32 %0, %1;" : "=r"(u) : "f"(x));
    return u;
}
__device__ __forceinline__ void mma_tf32(float& c0, float& c1, float& c2, float& c3,
                                         uint32_t a0, uint32_t a1, uint32_t a2, uint32_t a3,
                                         uint32_t b0, uint32_t b1) {
    asm volatile("mma.sync.aligned.m16n8k8.row.col.f32.tf32.tf32.f32 "
                 "{%0,%1,%2,%3},{%4,%5,%6,%7},{%8,%9},{%0,%1,%2,%3};"
                 : "+f"(c0), "+f"(c1), "+f"(c2), "+f"(c3)
                 : "r"(a0), "r"(a1), "r"(a2), "r"(a3), "r"(b0), "r"(b1));
}

// C[2000,512] = nodes[2000,4116] @ W[4116,512]; 128x64 block tile, 8 warps of 32x32
__global__ void k_gemm1_t(const float* __restrict__ Wg) {
    __shared__ uint32_t As[128 * 20];   // [m][k16] pad 20
    __shared__ uint32_t Bs[16 * 72];    // [k16][n64] pad 72
    const int M = BATCH * NNODES, N = 512, K = NODE_DIM;
    int bx = blockIdx.x, by = blockIdx.y;
    int tid = threadIdx.x;
    int warp = tid >> 5, lane = tid & 31;
    int gid = lane >> 2, tig = lane & 3;
    int wm = (warp >> 1) * 32, wn = (warp & 1) * 32;
    float c[2][4][4] = {};
    for (int k0 = 0; k0 < K; k0 += 16) {
        for (int i = tid; i < 2048; i += 256) {
            int m = i >> 4, kk = i & 15;
            int gm = by * 128 + m, gk = k0 + kk;
            float v = (gm < M && gk < K) ? g_nodes[(long)gm * K + gk] : 0.f;
            As[m * 20 + kk] = tf32r(v);
        }
        for (int i = tid; i < 1024; i += 256) {
            int kk = i >> 6, n = i & 63;
            int gk = k0 + kk;
            float v = (gk < K) ? Wg[(long)gk * N + bx * 64 + n] : 0.f;
            Bs[kk * 72 + n] = tf32r(v);
        }
        __syncthreads();
#pragma unroll
        for (int ks = 0; ks < 16; ks += 8) {
            uint32_t a[2][4], bf[4][2];
#pragma unroll
            for (int mi = 0; mi < 2; mi++) {
                int mb = wm + mi * 16;
                a[mi][0] = As[(mb + gid) * 20 + ks + tig];
                a[mi][1] = As[(mb + gid + 8) * 20 + ks + tig];
                a[mi][2] = As[(mb + gid) * 20 + ks + tig + 4];
                a[mi][3] = As[(mb + gid + 8) * 20 + ks + tig + 4];
            }
#pragma unroll
            for (int ni = 0; ni < 4; ni++) {
                int nb = wn + ni * 8;
                bf[ni][0] = Bs[(ks + tig) * 72 + nb + gid];
                bf[ni][1] = Bs[(ks + tig + 4) * 72 + nb + gid];
            }
#pragma unroll
            for (int mi = 0; mi < 2; mi++)
#pragma unroll
                for (int ni = 0; ni < 4; ni++)
                    mma_tf32(c[mi][ni][0], c[mi][ni][1], c[mi][ni][2], c[mi][ni][3],
                             a[mi][0], a[mi][1], a[mi][2], a[mi][3],
                             bf[ni][0], bf[ni][1]);
        }
        __syncthreads();
    }
#pragma unroll
    for (int mi = 0; mi < 2; mi++) {
        int r0 = by * 128 + wm + mi * 16 + gid;
        int r1 = r0 + 8;
#pragma unroll
        for (int ni = 0; ni < 4; ni++) {
            int gcol = bx * 64 + wn + ni * 8 + tig * 2;
            if (r0 < M) {
                float2 v = {c[mi][ni][0], c[mi][ni][1]};
                *(float2*)(g_gh + (long)r0 * N + gcol) = v;
            }
            if (r1 < M) {
                float2 v = {c[mi][ni][2], c[mi][ni][3]};
                *(float2*)(g_gh + (long)r1 * N + gcol) = v;
            }
        }
    }
}

// ---------------- generic tiled SGEMM (64x64x16) for gemm2 -------------------
__device__ __forceinline__ void gemm_body(const float* __restrict__ A,
                                          const float* __restrict__ B,
                                          float* __restrict__ C,
                                          int M, int N, int K) {
    __shared__ float As[16][65];
    __shared__ float Bs[16][64];
    int bx = blockIdx.x, by = blockIdx.y;
    int tid = threadIdx.x;
    int tr = tid >> 4, tc = tid & 15;
    float acc[4][4] = {};
    for (int k0 = 0; k0 < K; k0 += 16) {
        for (int i = tid; i < 64 * 16; i += 256) {
            int m = i >> 4, kk = i & 15;
            int gm = by * 64 + m, gk = k0 + kk;
            As[kk][m] = (gm < M && gk < K) ? A[(long)gm * K + gk] : 0.f;
        }
        for (int i = tid; i < 16 * 64; i += 256) {
            int kk = i >> 6, n = i & 63;
            int gk = k0 + kk, gn = bx * 64 + n;
            Bs[kk][n] = (gk < K && gn < N) ? B[(long)gk * N + gn] : 0.f;
        }
        __syncthreads();
#pragma unroll
        for (int kk = 0; kk < 16; kk++) {
            float a[4], bv[4];
#pragma unroll
            for (int i = 0; i < 4; i++) a[i] = As[kk][tr * 4 + i];
#pragma unroll
            for (int jq = 0; jq < 4; jq++) bv[jq] = Bs[kk][tc * 4 + jq];
#pragma unroll
            for (int i = 0; i < 4; i++)
#pragma unroll
                for (int jq = 0; jq < 4; jq++)
                    acc[i][jq] = fmaf(a[i], bv[jq], acc[i][jq]);
        }
        __syncthreads();
    }
    for (int i = 0; i < 4; i++) {
        int gm = by * 64 + tr * 4 + i;
        if (gm >= M) continue;
        for (int jq = 0; jq < 4; jq++) {
            int gn = bx * 64 + tc * 4 + jq;
            if (gn < N) C[(long)gm * N + gn] = acc[i][jq];
        }
    }
}
__global__ void k_gemm2(const float* __restrict__ W) {
    gemm_body(g_g1, W, g_h2g, BATCH * NNODES, 32, 512);
}

// ---------------- GAT1 attention scores ----------------
__global__ void k_scores1(const float* __restrict__ asrc, const float* __restrict__ adst) {
    int idx = blockIdx.x * 256 + threadIdx.x;
    if (idx >= BATCH * NNODES * 8) return;
    int h = idx & 7;
    int bn = idx >> 3;
    const float* hp = g_gh + (long)bn * 512 + h * 64;
    float s1 = 0.f, s2 = 0.f;
    for (int f = 0; f < 64; f++) {
        float v = hp[f];
        s1 = fmaf(v, asrc[h * 64 + f], s1);
        s2 = fmaf(v, adst[h * 64 + f], s2);
    }
    g_ssrc[idx] = s1;
    g_sdst[idx] = s2;
}

// ---------------- GAT1 softmax-attention + aggregate (10 i per block) --------
__global__ void k_att1(const float* __restrict__ bias) {
    extern __shared__ float sm[];
    float* swj = sm;               // [10][250][8] = 20000
    float* ss = sm + 20000;        // 2000
    float* sums = sm + 22000;      // 80
    int b = blockIdx.x / 25, ig = blockIdx.x % 25;
    int i0 = ig * 10;
    int tid = threadIdx.x;
    for (int i = tid; i < 2000; i += 256) ss[i] = g_ssrc[b * 2000 + i];
    __syncthreads();
    int warp = tid >> 5, lane = tid & 31;
    for (int task = warp; task < 80; task += 8) {
        int ii = task >> 3, h = task & 7;
        float d = g_sdst[(b * NNODES + i0 + ii) * 8 + h];
        float mx = -1e30f;
        for (int j = lane; j < NNODES; j += 32) {
            float e = d + ss[j * 8 + h];
            e = e > 0.f ? e : 0.2f * e;
            mx = fmaxf(mx, e);
        }
#pragma unroll
        for (int o = 16; o; o >>= 1) mx = fmaxf(mx, __shfl_xor_sync(0xffffffffu, mx, o));
        float smv = 0.f;
        for (int j = lane; j < NNODES; j += 32) {
            float e = d + ss[j * 8 + h];
            e = e > 0.f ? e : 0.2f * e;
            float wv = expf(e - mx);
            swj[(ii * NNODES + j) * 8 + h] = wv;
            smv += wv;
        }
#pragma unroll
        for (int o = 16; o; o >>= 1) smv += __shfl_xor_sync(0xffffffffu, smv, o);
        if (!lane) sums[ii * 8 + h] = smv;
    }
    __syncthreads();
    float acc0[10], acc1[10];
#pragma unroll
    for (int ii = 0; ii < 10; ii++) { acc0[ii] = 0.f; acc1[ii] = 0.f; }
    const float* Hb = g_gh + (long)b * NNODES * 512;
    int f0 = tid, f1 = tid + 256;
    int h0 = f0 >> 6, h1 = f1 >> 6;
    for (int j = 0; j < NNODES; j++) {
        float v0 = Hb[j * 512 + f0];
        float v1 = Hb[j * 512 + f1];
#pragma unroll
        for (int ii = 0; ii < 10; ii++) {
            acc0[ii] = fmaf(swj[(ii * NNODES + j) * 8 + h0], v0, acc0[ii]);
            acc1[ii] = fmaf(swj[(ii * NNODES + j) * 8 + h1], v1, acc1[ii]);
        }
    }
    float bi0 = bias[f0], bi1 = bias[f1];
    for (int ii = 0; ii < 10; ii++) {
        int i = i0 + ii;
        float* op = g_g1 + (long)(b * NNODES + i) * 512;
        float o0 = acc0[ii] / sums[ii * 8 + h0] + bi0;
        float o1 = acc1[ii] / sums[ii * 8 + h1] + bi1;
        op[f0] = o0 > 0.f ? o0 : 0.f;
        op[f1] = o1 > 0.f ? o1 : 0.f;
    }
}

// ---------------- GAT2 scores ----------------
__global__ void k_scores2(const float* __restrict__ asrc, const float* __restrict__ adst) {
    int idx = blockIdx.x * 256 + threadIdx.x;
    if (idx >= BATCH * NNODES) return;
    const float* hp = g_h2g + (long)idx * 32;
    float s1 = 0.f, s2 = 0.f;
    for (int f = 0; f < 32; f++) {
        float v = hp[f];
        s1 = fmaf(v, asrc[f], s1);
        s2 = fmaf(v, adst[f], s2);
    }
    g_s2src[idx] = s1;
    g_s2dst[idx] = s2;
}

// ---------------- GAT2 attention + aggregate ----------------
__global__ void k_att2(const float* __restrict__ bias) {
    __shared__ float sh[NNODES * 32];
    __shared__ float ssr[NNODES];
    __shared__ float wjs[8][NNODES];
    int b = blockIdx.x;
    int tid = threadIdx.x, warp = tid >> 5, lane = tid & 31;
    for (int i = tid; i < NNODES * 32; i += 256) sh[i] = g_h2g[b * NNODES * 32 + i];
    for (int i = tid; i < NNODES; i += 256) ssr[i] = g_s2src[b * NNODES + i];
    __syncthreads();
    float bi = bias[lane];
    for (int i = warp; i < NNODES; i += 8) {
        float d = g_s2dst[b * NNODES + i];
        float mx = -1e30f;
        for (int j = lane; j < NNODES; j += 32) {
            float e = d + ssr[j];
            e = e > 0.f ? e : 0.2f * e;
            mx = fmaxf(mx, e);
        }
#pragma unroll
        for (int o = 16; o; o >>= 1) mx = fmaxf(mx, __shfl_xor_sync(0xffffffffu, mx, o));
        float sum = 0.f;
        for (int j = lane; j < NNODES; j += 32) {
            float e = d + ssr[j];
            e = e > 0.f ? e : 0.2f * e;
            float wv = expf(e - mx);
            wjs[warp][j] = wv;
            sum += wv;
        }
#pragma unroll
        for (int o = 16; o; o >>= 1) sum += __shfl_xor_sync(0xffffffffu, sum, o);
        __syncwarp();
        float acc = 0.f;
        for (int j = 0; j < NNODES; j++) acc = fmaf(wjs[warp][j], sh[j * 32 + lane], acc);
        g_g2[(b * NNODES + i) * 32 + lane] = acc / sum + bi;
    }
}

// ---------------- mean-pool + FC head ----------------
__global__ void k_head(const float* __restrict__ fc1w, const float* __restrict__ fc1b,
                       const float* __restrict__ bg, const float* __restrict__ bb2,
                       const float* __restrict__ fc2w, const float* __restrict__ fc2b,
                       float* __restrict__ out, int write_emb) {
    __shared__ float semb[32];
    __shared__ float sz[128];
    int b = blockIdx.x, tid = threadIdx.x;
    if (tid < 32) {
        float s = 0.f;
        for (int i = 0; i < NNODES; i++) s += g_g2[(b * NNODES + i) * 32 + tid];
        s *= (1.f / 250.f);
        semb[tid] = s;
        if (write_emb) out[16 + b * 32 + tid] = s;
    }
    __syncthreads();
    {
        float z = fc1b[tid];
        for (int f = 0; f < 32; f++) z = fmaf(semb[f], fc1w[f * 128 + tid], z);
        z = z * (bg[tid] * rsqrtf(1.f + EPSV)) + bb2[tid];
        sz[tid] = z > 0.f ? z : 0.f;
    }
    __syncthreads();
    if (tid < 2) {
        float o = fc2b[tid];
        for (int q = 0; q < 128; q++) o = fmaf(sz[q], fc2w[q * 2 + tid], o);
        out[b * 2 + tid] = o;
    }
}

extern "C" void kernel_launch(void* const* d_in, const int* in_sizes, int n_in,
                              void* d_out, int out_size) {
    const float* x = (const float*)d_in[0];
    const float* sinc_w = (const float*)d_in[1];
    const float* conv1_w = (const float*)d_in[2];
    const float* conv1_b = (const float*)d_in[3];
    const float* bn1_g = (const float*)d_in[4];
    const float* bn1_b = (const float*)d_in[5];
    const float* conv2_w = (const float*)d_in[6];
    const float* conv2_b = (const float*)d_in[7];
    const float* bn2_g = (const float*)d_in[8];
    const float* bn2_b = (const float*)d_in[9];
    const float* gat1_W = (const float*)d_in[10];
    const float* gat1_asrc = (const float*)d_in[11];
    const float* gat1_adst = (const float*)d_in[12];
    const float* gat1_bias = (const float*)d_in[13];
    const float* gat2_W = (const float*)d_in[14];
    const float* gat2_asrc = (const float*)d_in[15];
    const float* gat2_adst = (const float*)d_in[16];
    const float* gat2_bias = (const float*)d_in[17];
    const float* fc1_w = (const float*)d_in[18];
    const float* fc1_b = (const float*)d_in[19];
    const float* bnf_g = (const float*)d_in[20];
    const float* bnf_b = (const float*)d_in[21];
    const float* fc2_w = (const float*)d_in[22];
    const float* fc2_b = (const float*)d_in[23];

    cudaFuncSetAttribute(k_fused, cudaFuncAttributeMaxDynamicSharedMemorySize, 20816 * 4);
    cudaFuncSetAttribute(k_att1, cudaFuncAttributeMaxDynamicSharedMemorySize, 22080 * 4);

    k_sinc<<<BATCH * SCC, 256>>>(x, sinc_w);
    k_stft<<<BATCH * NFR, 512>>>(x);

    dim3 gf(8, 64, BATCH);
    k_fused<<<gf, 256, 20816 * 4>>>(conv1_w, conv1_b, bn1_g, bn1_b,
                                    conv2_w, conv2_b, bn2_g, bn2_b);

    dim3 gg1(8, 16);
    k_gemm1_t<<<gg1, 256>>>(gat1_W);
    k_scores1<<<(BATCH * NNODES * 8 + 255) / 256, 256>>>(gat1_asrc, gat1_adst);
    k_att1<<<BATCH * 25, 256, 22080 * 4>>>(gat1_bias);

    dim3 gg2(1, 32);
    k_gemm2<<<gg2, 256>>>(gat2_W);
    k_scores2<<<(BATCH * NNODES + 255) / 256, 256>>>(gat2_asrc, gat2_adst);
    k_att2<<<BATCH, 256>>>(gat2_bias);

    int write_emb = (out_size >= 272) ? 1 : 0;
    k_head<<<BATCH, 128>>>(fc1_w, fc1_b, bnf_g, bnf_b, fc2_w, fc2_b,
                           (float*)d_out, write_emb);
}